// round 13
// baseline (speedup 1.0000x reference)
#include <cuda_runtime.h>
#include <cuda_bf16.h>
#include <math.h>
#include <stdint.h>

// Problem constants
#define B_   64
#define S_   256
#define DIM_ 512
#define H_   16
#define DH_  32
// -log2(10000)/32
#define ROPE_COEF (-0.41524101186092147f)

// ---------------------------------------------------------------------------
// Warp-level MMA helpers (sm_80+ features only; safe on target sm_103)
// ---------------------------------------------------------------------------
__device__ __forceinline__ uint32_t smem_to_u32(const void* smem_ptr) {
    uint32_t addr;
    asm("{ .reg .u64 tmp; cvta.to.shared.u64 tmp, %1; cvt.u32.u64 %0, tmp; }"
        : "=r"(addr) : "l"(smem_ptr));
    return addr;
}

__device__ __forceinline__ void ldm_x4(uint32_t* r, uint32_t addr) {
    asm volatile("ldmatrix.sync.aligned.m8n8.x4.shared.b16 {%0,%1,%2,%3}, [%4];"
                 : "=r"(r[0]), "=r"(r[1]), "=r"(r[2]), "=r"(r[3]) : "r"(addr));
}

__device__ __forceinline__ void ldm_x2t(uint32_t* r, uint32_t addr) {
    asm volatile("ldmatrix.sync.aligned.m8n8.x2.trans.shared.b16 {%0,%1}, [%2];"
                 : "=r"(r[0]), "=r"(r[1]) : "r"(addr));
}

__device__ __forceinline__ void mma16816(float* c, const uint32_t* a, const uint32_t* b) {
    asm volatile(
        "mma.sync.aligned.m16n8k16.row.col.f32.bf16.bf16.f32 "
        "{%0,%1,%2,%3}, {%4,%5,%6,%7}, {%8,%9}, {%0,%1,%2,%3};"
        : "+f"(c[0]), "+f"(c[1]), "+f"(c[2]), "+f"(c[3])
        : "r"(a[0]), "r"(a[1]), "r"(a[2]), "r"(a[3]), "r"(b[0]), "r"(b[1]));
}

__device__ __forceinline__ uint32_t pack_bf16(float x, float y) {
    __nv_bfloat162 p = __halves2bfloat162(__float2bfloat16(x), __float2bfloat16(y));
    return *(uint32_t*)&p;
}

#define CP_ASYNC16(dst, src) \
    asm volatile("cp.async.cg.shared.global [%0], [%1], 16;" :: "r"(dst), "l"(src))
#define CP_COMMIT() asm volatile("cp.async.commit_group;")
#define CP_WAIT0()  asm volatile("cp.async.wait_group 0;")

// ---------------------------------------------------------------------------
// Scratch
// ---------------------------------------------------------------------------
__device__ __nv_bfloat16 g_ah[16384 * 512];
__device__ __nv_bfloat16 g_al[16384 * 512];
__device__ __nv_bfloat16 g_wh[1536 * 512];
__device__ __nv_bfloat16 g_wl[1536 * 512];
#define QKV_ELEMS (B_ * H_ * S_ * DH_)
__device__ __nv_bfloat16 g_qh[QKV_ELEMS];
__device__ __nv_bfloat16 g_ql[QKV_ELEMS];
__device__ __nv_bfloat16 g_kh[QKV_ELEMS];
__device__ __nv_bfloat16 g_kl[QKV_ELEMS];
__device__ __nv_bfloat16 g_vh[QKV_ELEMS];
__device__ __nv_bfloat16 g_vl[QKV_ELEMS];

// ---------------------------------------------------------------------------
// Prep A: fp32 -> bf16 hi/lo split
// ---------------------------------------------------------------------------
__global__ __launch_bounds__(256) void prep_a_kernel(const float* __restrict__ hs) {
    size_t i = (size_t)blockIdx.x * 256 + threadIdx.x;
    float4 x = ((const float4*)hs)[i];
    __nv_bfloat16 h0 = __float2bfloat16(x.x);
    __nv_bfloat16 h1 = __float2bfloat16(x.y);
    __nv_bfloat16 h2 = __float2bfloat16(x.z);
    __nv_bfloat16 h3 = __float2bfloat16(x.w);
    __nv_bfloat16 l0 = __float2bfloat16(x.x - __bfloat162float(h0));
    __nv_bfloat16 l1 = __float2bfloat16(x.y - __bfloat162float(h1));
    __nv_bfloat16 l2 = __float2bfloat16(x.z - __bfloat162float(h2));
    __nv_bfloat16 l3 = __float2bfloat16(x.w - __bfloat162float(h3));
    __nv_bfloat162* AH2 = (__nv_bfloat162*)g_ah;
    __nv_bfloat162* AL2 = (__nv_bfloat162*)g_al;
    AH2[2 * i]     = __halves2bfloat162(h0, h1);
    AH2[2 * i + 1] = __halves2bfloat162(h2, h3);
    AL2[2 * i]     = __halves2bfloat162(l0, l1);
    AL2[2 * i + 1] = __halves2bfloat162(l2, l3);
}

// ---------------------------------------------------------------------------
// Prep W: transpose + bf16 hi/lo split.
// ---------------------------------------------------------------------------
__global__ __launch_bounds__(256) void prep_w_kernel(
    const float* __restrict__ Wq, const float* __restrict__ Wk, const float* __restrict__ Wv)
{
    __shared__ float t[32][33];
    const int tid = threadIdx.x;
    const int tx = tid & 31, ty = tid >> 5;
    const int mat = blockIdx.z;
    const float* W = (mat == 0) ? Wq : (mat == 1) ? Wk : Wv;
    const int n0 = blockIdx.x * 32, k0 = blockIdx.y * 32;

    #pragma unroll
    for (int j = 0; j < 4; j++) {
        int kk = ty + j * 8;
        t[kk][tx] = W[(size_t)(k0 + kk) * 512 + n0 + tx];
    }
    __syncthreads();
    #pragma unroll
    for (int j = 0; j < 4; j++) {
        int n = n0 + ty + j * 8;
        float v = t[tx][ty + j * 8];
        __nv_bfloat16 hi = __float2bfloat16(v);
        __nv_bfloat16 lo = __float2bfloat16(v - __bfloat162float(hi));
        size_t o = (size_t)(mat * 512 + n) * 512 + k0 + tx;
        g_wh[o] = hi;
        g_wl[o] = lo;
    }
}

// ---------------------------------------------------------------------------
// QKV GEMM: CTA tile 128x128, 512 thr (4x4 warps, warp 32x32), cp.async
// double buffer, K-chunk 32. 3-product hi/lo split. bias+RoPE epilogue.
// grid (12, 128): bx -> 128-col tile (mat = bx>>2), by -> 128-row tile.
// ---------------------------------------------------------------------------
#define QS_AH   0
#define QS_AL   10240
#define QS_BH   20480
#define QS_BL   30720
#define QS_BUF  40960
#define QS_TOTAL (2 * QS_BUF)   // 81920

__global__ __launch_bounds__(512) void qkv_mma_kernel(
    const float* __restrict__ bq, const float* __restrict__ bk, const float* __restrict__ bv)
{
    extern __shared__ char smem[];
    const uint32_t sb = smem_to_u32(smem);
    const int tid  = threadIdx.x;
    const int lane = tid & 31;
    const int warp = tid >> 5;
    const int wm = warp & 3;          // 0..3  (M)
    const int wn = warp >> 2;         // 0..3  (N)
    const int nbase = blockIdx.x * 128;
    const int r0    = blockIdx.y * 128;
    const int mat   = nbase >> 9;
    const bool rope = (mat < 2);

    float acc[2][4][4];
    #pragma unroll
    for (int i = 0; i < 2; i++)
        #pragma unroll
        for (int j = 0; j < 4; j++)
            #pragma unroll
            for (int k = 0; k < 4; k++) acc[i][j][k] = 0.0f;

    // cp.async mapping: row = tid>>2 (0..127), seg = (tid&3)*8 bf16
    const int grow = tid >> 2;
    const int gseg = (tid & 3) << 3;
    const size_t aSrc = (size_t)(r0 + grow) * 512 + gseg;
    const size_t bSrc = (size_t)(nbase + grow) * 512 + gseg;
    const uint32_t sdst = (uint32_t)(grow * 40 + gseg) * 2;

    // ldmatrix lane offsets
    const uint32_t aLdmRow = (uint32_t)(lane & 15);
    const uint32_t aLdmCol = (uint32_t)((lane >> 4) << 3);
    const uint32_t bLdmRow = (uint32_t)((lane & 7) + (((lane >> 4) & 1) << 3));
    const uint32_t bLdmCol = (uint32_t)(((lane >> 3) & 1) << 3);

    // preload chunk 0 into buffer 0
    {
        CP_ASYNC16(sb + QS_AH + sdst, &g_ah[aSrc]);
        CP_ASYNC16(sb + QS_AL + sdst, &g_al[aSrc]);
        CP_ASYNC16(sb + QS_BH + sdst, &g_wh[bSrc]);
        CP_ASYNC16(sb + QS_BL + sdst, &g_wl[bSrc]);
        CP_COMMIT();
    }

    for (int c = 0; c < 16; c++) {
        CP_WAIT0();
        __syncthreads();
        if (c < 15) {
            const uint32_t nb = sb + (uint32_t)((c + 1) & 1) * QS_BUF;
            const int kn = (c + 1) * 32;
            CP_ASYNC16(nb + QS_AH + sdst, &g_ah[aSrc + kn]);
            CP_ASYNC16(nb + QS_AL + sdst, &g_al[aSrc + kn]);
            CP_ASYNC16(nb + QS_BH + sdst, &g_wh[bSrc + kn]);
            CP_ASYNC16(nb + QS_BL + sdst, &g_wl[bSrc + kn]);
            CP_COMMIT();
        }

        const uint32_t bb = sb + (uint32_t)(c & 1) * QS_BUF;
        #pragma unroll
        for (int ks = 0; ks < 2; ks++) {
            uint32_t Ah[2][4], Al[2][4], Bh[2][4], Bl[2][4];
            #pragma unroll
            for (int mt = 0; mt < 2; mt++) {
                uint32_t eo = ((uint32_t)(wm * 32 + mt * 16) + aLdmRow) * 40
                              + (uint32_t)(ks * 16) + aLdmCol;
                ldm_x4(Ah[mt], bb + QS_AH + eo * 2);
                ldm_x4(Al[mt], bb + QS_AL + eo * 2);
            }
            #pragma unroll
            for (int p = 0; p < 2; p++) {
                uint32_t eo = ((uint32_t)(wn * 32 + p * 16) + bLdmRow) * 40
                              + (uint32_t)(ks * 16) + bLdmCol;
                ldm_x4(Bh[p], bb + QS_BH + eo * 2);
                ldm_x4(Bl[p], bb + QS_BL + eo * 2);
            }
            #pragma unroll
            for (int mt = 0; mt < 2; mt++)
                #pragma unroll
                for (int nt = 0; nt < 4; nt++) {
                    const uint32_t* bhp = &Bh[nt >> 1][(nt & 1) * 2];
                    const uint32_t* blp = &Bl[nt >> 1][(nt & 1) * 2];
                    mma16816(acc[mt][nt], Ah[mt], bhp);
                    mma16816(acc[mt][nt], Ah[mt], blp);
                    mma16816(acc[mt][nt], Al[mt], bhp);
                }
        }
    }

    // Epilogue: bias + RoPE, write bf16 hi/lo [B,H,S,DH]
    const float* bias = (mat == 0) ? bq : (mat == 1) ? bk : bv;
    __nv_bfloat16* dh = (mat == 0) ? g_qh : (mat == 1) ? g_kh : g_vh;
    __nv_bfloat16* dl = (mat == 0) ? g_ql : (mat == 1) ? g_kl : g_vl;

    #pragma unroll
    for (int nt = 0; nt < 4; nt++) {
        const int cg = nbase + wn * 32 + nt * 8 + (lane & 3) * 2;
        const int cW = cg & 511;
        const int head = cW >> 5;
        const int d0 = cW & 31;
        const float bi0 = bias[cW];
        const float bi1 = bias[cW + 1];
        const float ifr = rope ? exp2f((float)d0 * ROPE_COEF) : 0.0f;
        #pragma unroll
        for (int mt = 0; mt < 2; mt++) {
            const int rbase = r0 + wm * 32 + mt * 16 + (lane >> 2);
            #pragma unroll
            for (int half = 0; half < 2; half++) {
                const int r = rbase + half * 8;
                const int b = r >> 8;
                const int s = r & 255;
                float v0 = acc[mt][nt][half * 2 + 0] + bi0;
                float v1 = acc[mt][nt][half * 2 + 1] + bi1;
                if (rope) {
                    float sn, cs;
                    sincosf((float)s * ifr, &sn, &cs);
                    float t0 = v0 * cs - v1 * sn;
                    float t1 = v0 * sn + v1 * cs;
                    v0 = t0; v1 = t1;
                }
                __nv_bfloat16 h0 = __float2bfloat16(v0);
                __nv_bfloat16 h1 = __float2bfloat16(v1);
                float l0f = v0 - __bfloat162float(h0);
                float l1f = v1 - __bfloat162float(h1);
                size_t off = ((size_t)((b * H_ + head) * S_ + s) << 5) + d0;
                *(__nv_bfloat162*)&dh[off] = __halves2bfloat162(h0, h1);
                *(__nv_bfloat162*)&dl[off] = __halves2bfloat162(__float2bfloat16(l0f),
                                                                __float2bfloat16(l1f));
            }
        }
    }
}

// ---------------------------------------------------------------------------
// Attention, 512 threads = 16 warps per (b,h).
// S phase: warp w owns k-cols [w*16, w*16+16).
// PV: tile t = w&7 (m = t&1, d = t>>1), k-half = w>>3; partials combined in smem.
// ---------------------------------------------------------------------------
#define AS_KH 0
#define AS_KL 20480
#define AS_VH 40960
#define AS_VL 61440
#define AS_QH 81920
#define AS_QL 84480
#define AS_PH 87040
#define AS_PL 103936
#define AS_BI 120832
#define AS_MX 122880
#define AS_SM 125056
#define AS_CP 127232
#define AS_TOTAL 131328

__global__ __launch_bounds__(512) void attn_mma_kernel(
    const float* __restrict__ bias_table, float* __restrict__ out)
{
    extern __shared__ char smem[];
    const uint32_t sb = smem_to_u32(smem);
    const int tid = threadIdx.x;
    const int lane = tid & 31;
    const int w = tid >> 5;           // 0..15
    const int grp = lane >> 2;
    const int tid4 = lane & 3;
    const int bh = blockIdx.x;
    const int b = bh >> 4;
    const int h = bh & 15;
    const size_t base = (size_t)bh * (S_ * DH_);

    float* bsm  = (float*)(smem + AS_BI);
    float* pmax = (float*)(smem + AS_MX);   // [32][17]
    float* psum = (float*)(smem + AS_SM);   // [32][17]
    float* ctxp = (float*)(smem + AS_CP);   // [8][32][4]

    if (tid < 511) bsm[tid] = bias_table[tid * H_ + h];

    // K/V -> smem (stride 40 bf16). 512 threads: row = tid>>1, half = tid&1.
    {
        const int row = tid >> 1, half = tid & 1;
        const uint4* kh = (const uint4*)&g_kh[base + (size_t)row * 32 + half * 16];
        const uint4* kl = (const uint4*)&g_kl[base + (size_t)row * 32 + half * 16];
        const uint4* vh = (const uint4*)&g_vh[base + (size_t)row * 32 + half * 16];
        const uint4* vl = (const uint4*)&g_vl[base + (size_t)row * 32 + half * 16];
        const uint32_t d0 = (uint32_t)(row * 40 + half * 16) * 2;
        *(uint4*)(smem + AS_KH + d0)      = kh[0];
        *(uint4*)(smem + AS_KH + d0 + 16) = kh[1];
        *(uint4*)(smem + AS_KL + d0)      = kl[0];
        *(uint4*)(smem + AS_KL + d0 + 16) = kl[1];
        *(uint4*)(smem + AS_VH + d0)      = vh[0];
        *(uint4*)(smem + AS_VH + d0 + 16) = vh[1];
        *(uint4*)(smem + AS_VL + d0)      = vl[0];
        *(uint4*)(smem + AS_VL + d0 + 16) = vl[1];
    }

    // ldmatrix per-lane offsets
    const uint32_t a_row  = (uint32_t)(((lane >> 3) & 1) * 8 + (lane & 7));
    const uint32_t a_col8 = (uint32_t)(((lane >> 4) & 1) * 8);
    const uint32_t k_row  = (uint32_t)(((lane >> 4) & 1) * 8 + (lane & 7));
    const uint32_t k_col8 = (uint32_t)(((lane >> 3) & 1) * 8);
    const uint32_t v_row  = (uint32_t)(lane & 15);

    const int kb = w * 16;            // warp's k-col base for S
    const int pvt = w & 7;
    const int wm = pvt & 1;           // PV m-tile
    const int wd = pvt >> 1;          // PV d-tile
    const int khalf = w >> 3;         // PV k-half
    const float scale = 0.17677669529663687f;

    // Q-chunk load mapping
    const int qrow_l = tid >> 4;            // 0..31
    const int qd     = (tid & 15) * 2;

    for (int qc = 0; qc < 8; qc++) {
        {
            size_t src = base + (size_t)(qc * 32 + qrow_l) * 32 + qd;
            uint32_t dst = (uint32_t)(qrow_l * 40 + qd) * 2;
            *(uint32_t*)(smem + AS_QH + dst) = *(const uint32_t*)&g_qh[src];
            *(uint32_t*)(smem + AS_QL + dst) = *(const uint32_t*)&g_ql[src];
        }
        __syncthreads();

        // ---- S = Q K^T: 32 q rows x warp's 16 k-cols ----
        float acc[2][2][4];
        #pragma unroll
        for (int i = 0; i < 2; i++)
            #pragma unroll
            for (int j = 0; j < 2; j++)
                #pragma unroll
                for (int k2 = 0; k2 < 4; k2++) acc[i][j][k2] = 0.0f;

        #pragma unroll
        for (int ks = 0; ks < 2; ks++) {
            const uint32_t dbase = (uint32_t)(ks * 16);
            uint32_t Qh[2][4], Ql[2][4], Kh[4], Kl[4];
            #pragma unroll
            for (int mt = 0; mt < 2; mt++) {
                uint32_t eo = ((uint32_t)(mt * 16) + a_row) * 40 + dbase + a_col8;
                ldm_x4(Qh[mt], sb + AS_QH + eo * 2);
                ldm_x4(Ql[mt], sb + AS_QL + eo * 2);
            }
            {
                uint32_t eo = ((uint32_t)kb + k_row) * 40 + dbase + k_col8;
                ldm_x4(Kh, sb + AS_KH + eo * 2);
                ldm_x4(Kl, sb + AS_KL + eo * 2);
            }
            #pragma unroll
            for (int mt = 0; mt < 2; mt++)
                #pragma unroll
                for (int nt = 0; nt < 2; nt++) {
                    const uint32_t* bhp = &Kh[nt * 2];
                    const uint32_t* blp = &Kl[nt * 2];
                    mma16816(acc[mt][nt], Qh[mt], bhp);
                    mma16816(acc[mt][nt], Qh[mt], blp);
                    mma16816(acc[mt][nt], Ql[mt], bhp);
                }
        }

        // ---- softmax: row max over warp's 16 cols, then across 16 warps ----
        float m0[2][2];
        #pragma unroll
        for (int mt = 0; mt < 2; mt++) {
            float ma = -1e30f, mb = -1e30f;
            #pragma unroll
            for (int nt = 0; nt < 2; nt++) {
                ma = fmaxf(ma, fmaxf(acc[mt][nt][0], acc[mt][nt][1]));
                mb = fmaxf(mb, fmaxf(acc[mt][nt][2], acc[mt][nt][3]));
            }
            m0[mt][0] = ma; m0[mt][1] = mb;
        }
        #pragma unroll
        for (int mt = 0; mt < 2; mt++)
            #pragma unroll
            for (int hf = 0; hf < 2; hf++) {
                float m = m0[mt][hf];
                m = fmaxf(m, __shfl_xor_sync(0xffffffffu, m, 1));
                m = fmaxf(m, __shfl_xor_sync(0xffffffffu, m, 2));
                m0[mt][hf] = m;
            }
        if (tid4 == 0) {
            #pragma unroll
            for (int mt = 0; mt < 2; mt++)
                #pragma unroll
                for (int hf = 0; hf < 2; hf++)
                    pmax[(mt * 16 + grp + hf * 8) * 17 + w] = m0[mt][hf];
        }
        __syncthreads();
        float fm[2][2];
        #pragma unroll
        for (int mt = 0; mt < 2; mt++)
            #pragma unroll
            for (int hf = 0; hf < 2; hf++) {
                const int row = mt * 16 + grp + hf * 8;
                float m = pmax[row * 17];
                #pragma unroll
                for (int j = 1; j < 16; j++) m = fmaxf(m, pmax[row * 17 + j]);
                fm[mt][hf] = m;
            }

        // ---- exp + row sum ----
        float s0[2][2] = {{0.f, 0.f}, {0.f, 0.f}};
        #pragma unroll
        for (int mt = 0; mt < 2; mt++)
            #pragma unroll
            for (int nt = 0; nt < 2; nt++) {
                acc[mt][nt][0] = __expf((acc[mt][nt][0] - fm[mt][0]) * scale);
                acc[mt][nt][1] = __expf((acc[mt][nt][1] - fm[mt][0]) * scale);
                acc[mt][nt][2] = __expf((acc[mt][nt][2] - fm[mt][1]) * scale);
                acc[mt][nt][3] = __expf((acc[mt][nt][3] - fm[mt][1]) * scale);
                s0[mt][0] += acc[mt][nt][0] + acc[mt][nt][1];
                s0[mt][1] += acc[mt][nt][2] + acc[mt][nt][3];
            }
        #pragma unroll
        for (int mt = 0; mt < 2; mt++)
            #pragma unroll
            for (int hf = 0; hf < 2; hf++) {
                float s = s0[mt][hf];
                s += __shfl_xor_sync(0xffffffffu, s, 1);
                s += __shfl_xor_sync(0xffffffffu, s, 2);
                s0[mt][hf] = s;
            }
        if (tid4 == 0) {
            #pragma unroll
            for (int mt = 0; mt < 2; mt++)
                #pragma unroll
                for (int hf = 0; hf < 2; hf++)
                    psum[(mt * 16 + grp + hf * 8) * 17 + w] = s0[mt][hf];
        }
        __syncthreads();
        float inv[2][2];
        #pragma unroll
        for (int mt = 0; mt < 2; mt++)
            #pragma unroll
            for (int hf = 0; hf < 2; hf++) {
                const int row = mt * 16 + grp + hf * 8;
                float s = psum[row * 17];
                #pragma unroll
                for (int j = 1; j < 16; j++) s += psum[row * 17 + j];
                inv[mt][hf] = 1.0f / s;
            }

        // ---- p = e*inv + bias; hi/lo split into P smem ----
        #pragma unroll
        for (int mt = 0; mt < 2; mt++)
            #pragma unroll
            for (int nt = 0; nt < 2; nt++) {
                const int kcol = kb + nt * 8 + tid4 * 2;
                const int r0g = qc * 32 + mt * 16 + grp;
                float p0 = acc[mt][nt][0] * inv[mt][0] + bsm[r0g - kcol + 255];
                float p1 = acc[mt][nt][1] * inv[mt][0] + bsm[r0g - kcol + 254];
                float p2 = acc[mt][nt][2] * inv[mt][1] + bsm[r0g + 8 - kcol + 255];
                float p3 = acc[mt][nt][3] * inv[mt][1] + bsm[r0g + 8 - kcol + 254];
                __nv_bfloat16 h0 = __float2bfloat16(p0);
                __nv_bfloat16 h1 = __float2bfloat16(p1);
                __nv_bfloat16 h2 = __float2bfloat16(p2);
                __nv_bfloat16 h3 = __float2bfloat16(p3);
                const int row0 = mt * 16 + grp;
                uint32_t o0 = (uint32_t)(row0 * 264 + kcol) * 2;
                uint32_t o1 = (uint32_t)((row0 + 8) * 264 + kcol) * 2;
                *(uint32_t*)(smem + AS_PH + o0) = pack_bf16(p0, p1);
                *(uint32_t*)(smem + AS_PH + o1) = pack_bf16(p2, p3);
                *(uint32_t*)(smem + AS_PL + o0) =
                    pack_bf16(p0 - __bfloat162float(h0), p1 - __bfloat162float(h1));
                *(uint32_t*)(smem + AS_PL + o1) =
                    pack_bf16(p2 - __bfloat162float(h2), p3 - __bfloat162float(h3));
            }
        __syncthreads();

        // ---- ctx = P @ V: tile (wm, wd), k-half khalf ----
        float ctx[4] = {0.f, 0.f, 0.f, 0.f};
        #pragma unroll
        for (int kss = 0; kss < 8; kss++) {
            const int ks = khalf * 8 + kss;
            uint32_t Ph[4], Pl[4], Vh2[2], Vl2[2];
            uint32_t eoP = ((uint32_t)(wm * 16) + a_row) * 264 + (uint32_t)(ks * 16) + a_col8;
            ldm_x4(Ph, sb + AS_PH + eoP * 2);
            ldm_x4(Pl, sb + AS_PL + eoP * 2);
            uint32_t eoV = ((uint32_t)(ks * 16) + v_row) * 40 + (uint32_t)(wd * 8);
            ldm_x2t(Vh2, sb + AS_VH + eoV * 2);
            ldm_x2t(Vl2, sb + AS_VL + eoV * 2);
            mma16816(ctx, Ph, Vh2);
            mma16816(ctx, Ph, Vl2);
            mma16816(ctx, Pl, Vh2);
        }

        // upper-half warps deposit partials; lower-half combine + write
        if (w >= 8) {
            float* cp = &ctxp[((w - 8) * 32 + lane) * 4];
            cp[0] = ctx[0]; cp[1] = ctx[1]; cp[2] = ctx[2]; cp[3] = ctx[3];
        }
        __syncthreads();
        if (w < 8) {
            const float* cp = &ctxp[(w * 32 + lane) * 4];
            const int qrow = qc * 32 + wm * 16 + grp;
            const int d = wd * 8 + tid4 * 2;
            float* o0 = &out[(size_t)(b * S_ + qrow) * DIM_ + h * DH_ + d];
            float* o1 = &out[(size_t)(b * S_ + qrow + 8) * DIM_ + h * DH_ + d];
            *(float2*)o0 = make_float2(ctx[0] + cp[0], ctx[1] + cp[1]);
            *(float2*)o1 = make_float2(ctx[2] + cp[2], ctx[3] + cp[3]);
        }
        __syncthreads();
    }
}

// ---------------------------------------------------------------------------
extern "C" void kernel_launch(void* const* d_in, const int* in_sizes, int n_in,
                              void* d_out, int out_size)
{
    const float* hs = (const float*)d_in[0];
    const float* Wq = (const float*)d_in[1];
    const float* bq = (const float*)d_in[2];
    const float* Wk = (const float*)d_in[3];
    const float* bk = (const float*)d_in[4];
    const float* Wv = (const float*)d_in[5];
    const float* bv = (const float*)d_in[6];
    const float* bias_table = (const float*)d_in[7];
    float* out = (float*)d_out;

    (void)in_sizes; (void)n_in; (void)out_size;

    cudaFuncSetAttribute(qkv_mma_kernel, cudaFuncAttributeMaxDynamicSharedMemorySize,
                         QS_TOTAL);
    cudaFuncSetAttribute(attn_mma_kernel, cudaFuncAttributeMaxDynamicSharedMemorySize,
                         AS_TOTAL);

    prep_a_kernel<<<8192, 256>>>(hs);
    prep_w_kernel<<<dim3(16, 16, 3), 256>>>(Wq, Wk, Wv);
    qkv_mma_kernel<<<dim3(12, 128), 512, QS_TOTAL>>>(bq, bk, bv);
    attn_mma_kernel<<<B_ * H_, 512, AS_TOTAL>>>(bias_table, out);
}